// round 12
// baseline (speedup 1.0000x reference)
#include <cuda_runtime.h>
#include <cuda_bf16.h>
#include <cstdint>
#include <math.h>

// ============================================================
// x(1024,512) f32, prototypes(100,10,512) f32, log_dist_scales(100,10,512) f32
// out(1024,100) = logsumexp_p( -( sum_d w*(x-p)^2 ) ),  w = exp(ls)
// dist = t1 + (-2*t2 + t3)
// R12: BM=64/BN=40 grid-400 granularity (R10 win) + 32x40 warp tiles (R9's
// lower t_u) via 64-thread 2-warp CTAs, 6 CTAs/SM. Widened proto prep
// (8 elems/thread, uint4 stores). t3 prefetched to regs before k-loop.
// Fast path (ls==0): K=512, t1 slid out of LSE.
// ============================================================

#define MB 1024
#define KD 1024

#define BM 64
#define BN 40
#define BK 64
#define NKT (KD / BK)   // 16
#define NTHREADS 64

// ---------------- device scratch ----------------
__device__ __nv_bfloat16 g_A[MB * KD];     // [b][k]  k<512: x^2, k>=512: x
__device__ __nv_bfloat16 g_Bm[1000 * KD];  // [cp][k] k<512: w,   k>=512: -2wp
__device__ float g_t3[1000];               // sum w p^2
__device__ float g_t1[MB];                 // sum x^2 (fp32 exact)
__device__ int   g_flag;                   // sticky: 1 if any ls != 0 (zero-init)

// ---------------- helpers ----------------
__device__ __forceinline__ uint32_t smem_u32(const void* p) {
    uint32_t a;
    asm("{ .reg .u64 t; cvta.to.shared.u64 t, %1; cvt.u32.u64 %0, t; }" : "=r"(a) : "l"(p));
    return a;
}
__device__ __forceinline__ uint32_t sw128(uint32_t off) {
    return off ^ ((off >> 3) & 0x70);
}
#define CP_ASYNC16(dst, src) \
    asm volatile("cp.async.cg.shared.global [%0], [%1], 16;" :: "r"(dst), "l"(src) : "memory")
#define CP_COMMIT() asm volatile("cp.async.commit_group;" ::: "memory")
#define CP_WAIT1()  asm volatile("cp.async.wait_group 1;" ::: "memory")
#define CP_WAIT0()  asm volatile("cp.async.wait_group 0;" ::: "memory")

#define LDMATRIX_X4(r0, r1, r2, r3, addr) \
    asm volatile("ldmatrix.sync.aligned.m8n8.x4.shared.b16 {%0,%1,%2,%3}, [%4];" \
                 : "=r"(r0), "=r"(r1), "=r"(r2), "=r"(r3) : "r"(addr))
#define LDMATRIX_X2(r0, r1, addr) \
    asm volatile("ldmatrix.sync.aligned.m8n8.x2.shared.b16 {%0,%1}, [%2];" \
                 : "=r"(r0), "=r"(r1) : "r"(addr))
#define MMA_16816(c0, c1, c2, c3, a0, a1, a2, a3, b0, b1) \
    asm volatile("mma.sync.aligned.m16n8k16.row.col.f32.bf16.bf16.f32 " \
                 "{%0,%1,%2,%3}, {%4,%5,%6,%7}, {%8,%9}, {%0,%1,%2,%3};" \
                 : "+f"(c0), "+f"(c1), "+f"(c2), "+f"(c3) \
                 : "r"(a0), "r"(a1), "r"(a2), "r"(a3), "r"(b0), "r"(b1))

// ---------------- prep: x + t1 (blocks 0..255), proto + t3 + flag (blocks 256..505)
__global__ void prep_kernel(const float* __restrict__ x,
                            const float* __restrict__ proto,
                            const float* __restrict__ ls) {
    const int tid = threadIdx.x;
    if (blockIdx.x < 256) {
        int idx = blockIdx.x * 256 + tid;
        int b  = idx >> 6;
        int d0 = (idx & 63) * 8;
        const float4* src = reinterpret_cast<const float4*>(x) + idx * 2;
        float4 v0 = src[0], v1 = src[1];
        __nv_bfloat162 hs[4], hx[4];
        hs[0] = __floats2bfloat162_rn(v0.x * v0.x, v0.y * v0.y);
        hs[1] = __floats2bfloat162_rn(v0.z * v0.z, v0.w * v0.w);
        hs[2] = __floats2bfloat162_rn(v1.x * v1.x, v1.y * v1.y);
        hs[3] = __floats2bfloat162_rn(v1.z * v1.z, v1.w * v1.w);
        hx[0] = __floats2bfloat162_rn(v0.x, v0.y);
        hx[1] = __floats2bfloat162_rn(v0.z, v0.w);
        hx[2] = __floats2bfloat162_rn(v1.x, v1.y);
        hx[3] = __floats2bfloat162_rn(v1.z, v1.w);
        *reinterpret_cast<uint4*>(g_A + (size_t)b * KD + d0)       = *reinterpret_cast<uint4*>(hs);
        *reinterpret_cast<uint4*>(g_A + (size_t)b * KD + 512 + d0) = *reinterpret_cast<uint4*>(hx);
        float s = v0.x * v0.x + v0.y * v0.y + v0.z * v0.z + v0.w * v0.w
                + v1.x * v1.x + v1.y * v1.y + v1.z * v1.z + v1.w * v1.w;
        #pragma unroll
        for (int o = 16; o > 0; o >>= 1) s += __shfl_xor_sync(0xffffffffu, s, o);
        __shared__ float red[8];
        if ((tid & 31) == 0) red[tid >> 5] = s;
        __syncthreads();
        if ((tid & 63) == 0) {
            int w0 = tid >> 5;
            g_t1[b] = red[w0] + red[w0 + 1];
        }
    } else {
        // 4 cp rows per block (64 threads/row); 8 elems per thread
        int cp = (blockIdx.x - 256) * 4 + (tid >> 6);
        int d0 = (tid & 63) * 8;
        const float4* lsrc = reinterpret_cast<const float4*>(ls + (size_t)cp * 512 + d0);
        const float4* psrc = reinterpret_cast<const float4*>(proto + (size_t)cp * 512 + d0);
        float4 l0 = lsrc[0], l1 = lsrc[1];
        float4 p0 = psrc[0], p1 = psrc[1];
        bool nzb = (l0.x != 0.f) || (l0.y != 0.f) || (l0.z != 0.f) || (l0.w != 0.f)
                || (l1.x != 0.f) || (l1.y != 0.f) || (l1.z != 0.f) || (l1.w != 0.f);
        unsigned nz = __ballot_sync(0xffffffffu, nzb);
        if (nz && (tid & 31) == 0) atomicOr(&g_flag, 1);   // sticky across replays
        float w0 = expf(l0.x), w1 = expf(l0.y), w2 = expf(l0.z), w3 = expf(l0.w);
        float w4 = expf(l1.x), w5 = expf(l1.y), w6 = expf(l1.z), w7 = expf(l1.w);
        __nv_bfloat162 hw[4], hp[4];
        hw[0] = __floats2bfloat162_rn(w0, w1);
        hw[1] = __floats2bfloat162_rn(w2, w3);
        hw[2] = __floats2bfloat162_rn(w4, w5);
        hw[3] = __floats2bfloat162_rn(w6, w7);
        hp[0] = __floats2bfloat162_rn(-2.0f * w0 * p0.x, -2.0f * w1 * p0.y);
        hp[1] = __floats2bfloat162_rn(-2.0f * w2 * p0.z, -2.0f * w3 * p0.w);
        hp[2] = __floats2bfloat162_rn(-2.0f * w4 * p1.x, -2.0f * w5 * p1.y);
        hp[3] = __floats2bfloat162_rn(-2.0f * w6 * p1.z, -2.0f * w7 * p1.w);
        *reinterpret_cast<uint4*>(g_Bm + (size_t)cp * KD + d0)       = *reinterpret_cast<uint4*>(hw);
        *reinterpret_cast<uint4*>(g_Bm + (size_t)cp * KD + 512 + d0) = *reinterpret_cast<uint4*>(hp);
        float acc = w0 * p0.x * p0.x + w1 * p0.y * p0.y + w2 * p0.z * p0.z + w3 * p0.w * p0.w
                  + w4 * p1.x * p1.x + w5 * p1.y * p1.y + w6 * p1.z * p1.z + w7 * p1.w * p1.w;
        #pragma unroll
        for (int o = 16; o > 0; o >>= 1) acc += __shfl_xor_sync(0xffffffffu, acc, o);
        __shared__ float red2[8];
        if ((tid & 31) == 0) red2[tid >> 5] = acc;
        __syncthreads();
        if ((tid & 63) == 0) {
            int w0i = tid >> 5;
            g_t3[cp] = red2[w0i] + red2[w0i + 1];
        }
    }
}

// ---------------- GEMM + fused LSE: BM=64, BN=40, 64 threads (2 warps of 32x40) ----------------
// SMEM: A[2][64][64] bf16 (8KB/stage), B[2][40][64] bf16 (5KB/stage) = 26KB
#define SA_OFF(s) ((s) * 8192)
#define SB_OFF(s) (16384 + (s) * 5120)
#define SMEM_TOTAL  (16384 + 2 * 5120)      // 26624
#define SST_STRIDE  44
#define T3_OFF      (64 * SST_STRIDE * 4)   // 11264 (inside A region, post-loop use)

__global__ __launch_bounds__(NTHREADS, 6) void gemm_lse_kernel(float* __restrict__ out) {
    extern __shared__ char smem[];
    const uint32_t sbase = smem_u32(smem);
    const int tid = threadIdx.x;
    const int wid = tid >> 5;    // 0..1
    const int lid = tid & 31;
    const int m0 = blockIdx.y * BM;
    const int n0 = blockIdx.x * BN;

    const int flag = g_flag;
    const int kstart = flag ? 0 : 8;   // fast path: only the x-part (k 512..1023)

    // prefetch t3 for this class tile into regs (hides gmem latency behind k-loop)
    float t3reg = (tid < 40) ? g_t3[n0 + tid] : 0.f;

    // ---- load plan: A 512 chunks (8/thread); B 320 chunks (5/thread, exact)
    const __nv_bfloat16* a_src[8];
    uint32_t a_dst[8];
    #pragma unroll
    for (int i = 0; i < 8; i++) {
        int q = tid + i * NTHREADS;
        int r = q >> 3, c = q & 7;
        a_src[i] = g_A + (size_t)(m0 + r) * KD + c * 8;
        a_dst[i] = sw128((uint32_t)r * 128u + (uint32_t)c * 16u);
    }
    const __nv_bfloat16* b_src[5];
    uint32_t b_dst[5];
    #pragma unroll
    for (int i = 0; i < 5; i++) {
        int q = tid + i * NTHREADS;
        int r = q >> 3, c = q & 7;
        b_src[i] = g_Bm + (size_t)(n0 + r) * KD + c * 8;
        b_dst[i] = sw128((uint32_t)r * 128u + (uint32_t)c * 16u);
    }

    // warp layout: 2 warps stacked in M; warp tile 32 x 40
    const int wm = wid * 32;

    float acc[2][5][4];
    #pragma unroll
    for (int mf = 0; mf < 2; mf++)
        #pragma unroll
        for (int nf = 0; nf < 5; nf++)
            #pragma unroll
            for (int i = 0; i < 4; i++) acc[mf][nf][i] = 0.f;

    // ldmatrix swizzled offsets: A 2 x4; B 2 x4 (nf pairs) + 1 x2 (nf=4)
    const int l4 = lid & 15;
    uint32_t a_lm_off[2][4];
    uint32_t b4_off[2][4];
    uint32_t b2_off[4];
    #pragma unroll
    for (int ks = 0; ks < 4; ks++) {
        #pragma unroll
        for (int mf = 0; mf < 2; mf++) {
            uint32_t r = wm + mf * 16 + (lid & 15);
            uint32_t ch = ks * 2 + (lid >> 4);
            a_lm_off[mf][ks] = sw128(r * 128u + ch * 16u);
        }
        #pragma unroll
        for (int j = 0; j < 2; j++) {
            uint32_t r = j * 16 + (lid >> 4) * 8 + (lid & 7);
            uint32_t ch = ks * 2 + ((lid >> 3) & 1);
            b4_off[j][ks] = sw128(r * 128u + ch * 16u);
        }
        {
            uint32_t r = 32 + (l4 & 7);
            uint32_t ch = ks * 2 + (l4 >> 3);
            b2_off[ks] = sw128(r * 128u + ch * 16u);
        }
    }

    // ---- prologue: tile kstart ----
    {
        int buf = kstart & 1;
        uint32_t sa = sbase + SA_OFF(buf), sb = sbase + SB_OFF(buf);
        #pragma unroll
        for (int i = 0; i < 8; i++) CP_ASYNC16(sa + a_dst[i], a_src[i] + kstart * BK);
        #pragma unroll
        for (int i = 0; i < 5; i++) CP_ASYNC16(sb + b_dst[i], b_src[i] + kstart * BK);
        CP_COMMIT();
    }

    for (int kt = kstart; kt < NKT; kt++) {
        if (kt + 1 < NKT) {
            int nb = (kt + 1) & 1;
            uint32_t sa = sbase + SA_OFF(nb), sb = sbase + SB_OFF(nb);
            #pragma unroll
            for (int i = 0; i < 8; i++) CP_ASYNC16(sa + a_dst[i], a_src[i] + (kt + 1) * BK);
            #pragma unroll
            for (int i = 0; i < 5; i++) CP_ASYNC16(sb + b_dst[i], b_src[i] + (kt + 1) * BK);
            CP_COMMIT();
            CP_WAIT1();
        } else {
            CP_WAIT0();
        }
        __syncthreads();

        const uint32_t sa = sbase + SA_OFF(kt & 1);
        const uint32_t sb = sbase + SB_OFF(kt & 1);
        #pragma unroll
        for (int ks = 0; ks < 4; ks++) {
            uint32_t a[2][4], b[5][2];
            #pragma unroll
            for (int mf = 0; mf < 2; mf++)
                LDMATRIX_X4(a[mf][0], a[mf][1], a[mf][2], a[mf][3], sa + a_lm_off[mf][ks]);
            LDMATRIX_X4(b[0][0], b[0][1], b[1][0], b[1][1], sb + b4_off[0][ks]);
            LDMATRIX_X4(b[2][0], b[2][1], b[3][0], b[3][1], sb + b4_off[1][ks]);
            LDMATRIX_X2(b[4][0], b[4][1], sb + b2_off[ks]);
            #pragma unroll
            for (int mf = 0; mf < 2; mf++)
                #pragma unroll
                for (int nf = 0; nf < 5; nf++)
                    MMA_16816(acc[mf][nf][0], acc[mf][nf][1], acc[mf][nf][2], acc[mf][nf][3],
                              a[mf][0], a[mf][1], a[mf][2], a[mf][3], b[nf][0], b[nf][1]);
        }
        __syncthreads();
    }

    // ---- fused epilogue: fragments -> SMEM stage -> per-(row,class) logsumexp ----
    float* sst = reinterpret_cast<float*>(smem);            // [64][44]
    float* st3 = reinterpret_cast<float*>(smem + T3_OFF);   // [40]
    if (tid < 40) st3[tid] = t3reg;

    const int qr = lid >> 2;
    const int qc = (lid & 3) * 2;
    #pragma unroll
    for (int mf = 0; mf < 2; mf++) {
        int row = wm + mf * 16 + qr;
        #pragma unroll
        for (int nf = 0; nf < 5; nf++) {
            int col = nf * 8 + qc;
            *reinterpret_cast<float2*>(&sst[row * SST_STRIDE + col]) =
                make_float2(acc[mf][nf][0], acc[mf][nf][1]);
            *reinterpret_cast<float2*>(&sst[(row + 8) * SST_STRIDE + col]) =
                make_float2(acc[mf][nf][2], acc[mf][nf][3]);
        }
    }
    __syncthreads();

    // 64 rows x 4 classes = 256 tasks, 4 per thread
    const int c0 = blockIdx.x * 4;
    #pragma unroll
    for (int i = 0; i < 4; i++) {
        int task = tid + i * NTHREADS;
        int row = task >> 2;
        int cls = task & 3;
        const float* sp = &sst[row * SST_STRIDE + cls * 10];
        const float* tp = &st3[cls * 10];
        float v[10], mx = -3.4e38f;
        #pragma unroll
        for (int p = 0; p < 10; p++) {
            v[p] = -(sp[p] + tp[p]);
            mx = fmaxf(mx, v[p]);
        }
        float s = 0.f;
        #pragma unroll
        for (int p = 0; p < 10; p++) s += expf(v[p] - mx);
        float t1v = flag ? 0.f : g_t1[m0 + row];   // fast path: t1 slid out of lse
        out[(size_t)(m0 + row) * 100 + c0 + cls] = mx + logf(s) - t1v;
    }
}

// ---------------- launch ----------------
extern "C" void kernel_launch(void* const* d_in, const int* in_sizes, int n_in,
                              void* d_out, int out_size) {
    const float* x     = (const float*)d_in[0];  // (1024, 512)
    const float* proto = (const float*)d_in[1];  // (100, 10, 512)
    const float* ls    = (const float*)d_in[2];  // (100, 10, 512)
    float* out = (float*)d_out;                  // (1024, 100)

    cudaFuncSetAttribute(gemm_lse_kernel, cudaFuncAttributeMaxDynamicSharedMemorySize, SMEM_TOTAL);

    prep_kernel<<<506, 256>>>(x, proto, ls);     // x+t1 (256 blocks) | proto+t3+flag (250)
    gemm_lse_kernel<<<dim3(25, MB / BM), NTHREADS, SMEM_TOTAL>>>(out);
}